// round 14
// baseline (speedup 1.0000x reference)
#include <cuda_runtime.h>
#include <cuda.h>

// LeadLagSignature depth-3, lead-lag of 16-point sliding patches.
// R12 = R11 scaled to CHUNK=4: full recursion for p0, three sliding-window
// Chen updates for p0+1..p0+3. Two SW128 tiles ping-pong through TMA bulk
// stores (wait_group<=1 gates reuse); two s2/s1 buffers ping-pong the state.

#define DIM 8
#define PATCH 16
#define NDIFF 15
#define LLD 16
#define CHUNK 4
#define NDT (NDIFF + CHUNK - 1)                  // 18 diffs per block
#define TILE_BYTES (LLD * LLD * LLD * 4)         // 16384
#define SD_OFF     (2 * TILE_BYTES)              // 32768
#define S2_OFF     (SD_OFF + NDT * DIM * 4)      // +576
#define S1_OFF     (S2_OFF + 2 * 16 * 20 * 4)    // +2560
#define SMEM_TOTAL (S1_OFF + 2 * 16 * 4)         // 36032

typedef unsigned long long u64;

__device__ __forceinline__ u64 ffma2(u64 a, u64 b, u64 c) {
    u64 d;
    asm("fma.rn.f32x2 %0, %1, %2, %3;" : "=l"(d) : "l"(a), "l"(b), "l"(c));
    return d;
}

__device__ __forceinline__ u64 bcast2(float f) {
    unsigned int r = __float_as_uint(f);
    u64 d;
    asm("mov.b64 %0, {%1, %1};" : "=l"(d) : "r"(r));
    return d;
}

__device__ __forceinline__ unsigned int smem_u32(const void* p) {
    unsigned int a;
    asm("{ .reg .u64 t; cvta.to.shared.u64 t, %1; cvt.u32.u64 %0, t; }"
        : "=r"(a) : "l"(p));
    return a;
}

__device__ __forceinline__ unsigned int sw128(unsigned int byte_off) {
    return byte_off ^ ((byte_off >> 3) & 0x70);
}

// ---- right-append of the two increments (lead then lag) of diff vector dv ----
template <bool ALEAD>
__device__ __forceinline__ void right_pair(const float* __restrict__ dv,
                                           int ai, int bi,
                                           u64* s3b, u64* s3g,
                                           float& s2b, float& s2g, float& s1a)
{
    const float C2 = 0.5f;
    const float C3 = 1.0f / 6.0f;
    const ulonglong2 pA = *reinterpret_cast<const ulonglong2*>(dv);
    const ulonglong2 pB = *reinterpret_cast<const ulonglong2*>(dv + 4);
    const float va = dv[ai];
    const float vb = dv[bi];

    float Fb, F2b, Fg, F2g;
    if (ALEAD) {
        Fg = s2g;
        const float cs1 = C2 * s1a;
        const float u   = fmaf(C3, va, cs1);
        Fb  = fmaf(vb, u, s2b);
        const float w   = fmaf(C2, va, s1a);
        s2b = fmaf(vb, w, s2b);
        s1a += va;
        F2b = s2b;
        const float h   = C2 * s1a;
        F2g = fmaf(vb, h, s2g);
        s2g = fmaf(vb, s1a, s2g);
    } else {
        const float cs1 = C2 * s1a;
        Fb  = fmaf(vb, cs1, s2b);
        s2b = fmaf(vb, s1a, s2b);
        Fg  = s2g;
        F2b = s2b;
        const float u   = fmaf(C3, va, cs1);
        F2g = fmaf(vb, u, s2g);
        const float w   = fmaf(C2, va, s1a);
        s2g = fmaf(vb, w, s2g);
        s1a += va;
    }

    const u64 Fbp  = bcast2(Fb);
    const u64 F2bp = bcast2(F2b);
    const u64 Fgp  = bcast2(Fg);
    const u64 F2gp = bcast2(F2g);

    s3b[0] = ffma2(Fbp,  pA.x, s3b[0]);
    s3b[1] = ffma2(Fbp,  pA.y, s3b[1]);
    s3b[2] = ffma2(Fbp,  pB.x, s3b[2]);
    s3b[3] = ffma2(Fbp,  pB.y, s3b[3]);
    s3b[4] = ffma2(F2bp, pA.x, s3b[4]);
    s3b[5] = ffma2(F2bp, pA.y, s3b[5]);
    s3b[6] = ffma2(F2bp, pB.x, s3b[6]);
    s3b[7] = ffma2(F2bp, pB.y, s3b[7]);
    s3g[0] = ffma2(Fgp,  pA.x, s3g[0]);
    s3g[1] = ffma2(Fgp,  pA.y, s3g[1]);
    s3g[2] = ffma2(Fgp,  pB.x, s3g[2]);
    s3g[3] = ffma2(Fgp,  pB.y, s3g[3]);
    s3g[4] = ffma2(F2gp, pA.x, s3g[4]);
    s3g[5] = ffma2(F2gp, pA.y, s3g[5]);
    s3g[6] = ffma2(F2gp, pB.x, s3g[6]);
    s3g[7] = ffma2(F2gp, pB.y, s3g[7]);
}

// ---- combined left-removal by C = e^{-G(d)} ⊗ e^{-L(d)} (verified R5/R11) ----
template <bool ALEAD>
__device__ __forceinline__ void left_remove(const float* __restrict__ dOld,
                                            const float* __restrict__ s2rowb,
                                            const float* __restrict__ s2rowg,
                                            const float* __restrict__ s1old,
                                            int ai, int b,
                                            u64* s3b, u64* s3g,
                                            float& s2b, float& s2g, float& s1a)
{
    const float Da = dOld[ai];
    const float Db = dOld[b];
    const ulonglong2 v0 = *reinterpret_cast<const ulonglong2*>(dOld);
    const ulonglong2 v1 = *reinterpret_cast<const ulonglong2*>(dOld + 4);
    const u64 C1 = bcast2(-Da);
    const float t = Da * Db;

    const ulonglong2 q0 = *reinterpret_cast<const ulonglong2*>(s1old);
    const ulonglong2 q1 = *reinterpret_cast<const ulonglong2*>(s1old + 4);
    const ulonglong2 q2 = *reinterpret_cast<const ulonglong2*>(s1old + 8);
    const ulonglong2 q3 = *reinterpret_cast<const ulonglong2*>(s1old + 12);
    const float S1b  = s1old[b];
    const float S1b8 = s1old[b + 8];

    const ulonglong2 rb0 = *reinterpret_cast<const ulonglong2*>(s2rowb);
    const ulonglong2 rb1 = *reinterpret_cast<const ulonglong2*>(s2rowb + 4);
    const ulonglong2 rb2 = *reinterpret_cast<const ulonglong2*>(s2rowb + 8);
    const ulonglong2 rb3 = *reinterpret_cast<const ulonglong2*>(s2rowb + 12);
    const ulonglong2 rg0 = *reinterpret_cast<const ulonglong2*>(s2rowg);
    const ulonglong2 rg1 = *reinterpret_cast<const ulonglong2*>(s2rowg + 4);
    const ulonglong2 rg2 = *reinterpret_cast<const ulonglong2*>(s2rowg + 8);
    const ulonglong2 rg3 = *reinterpret_cast<const ulonglong2*>(s2rowg + 12);

    s3b[0] = ffma2(C1, rb0.x, s3b[0]);
    s3b[1] = ffma2(C1, rb0.y, s3b[1]);
    s3b[2] = ffma2(C1, rb1.x, s3b[2]);
    s3b[3] = ffma2(C1, rb1.y, s3b[3]);
    s3b[4] = ffma2(C1, rb2.x, s3b[4]);
    s3b[5] = ffma2(C1, rb2.y, s3b[5]);
    s3b[6] = ffma2(C1, rb3.x, s3b[6]);
    s3b[7] = ffma2(C1, rb3.y, s3b[7]);
    s3g[0] = ffma2(C1, rg0.x, s3g[0]);
    s3g[1] = ffma2(C1, rg0.y, s3g[1]);
    s3g[2] = ffma2(C1, rg1.x, s3g[2]);
    s3g[3] = ffma2(C1, rg1.y, s3g[3]);
    s3g[4] = ffma2(C1, rg2.x, s3g[4]);
    s3g[5] = ffma2(C1, rg2.y, s3g[5]);
    s3g[6] = ffma2(C1, rg3.x, s3g[6]);
    s3g[7] = ffma2(C1, rg3.y, s3g[7]);

    if (ALEAD) {
        const u64 C2b = bcast2(0.5f * t);
        const u64 K3l = bcast2(-t * (1.0f / 6.0f));
        s3b[0] = ffma2(C2b, q0.x, s3b[0]);
        s3b[1] = ffma2(C2b, q0.y, s3b[1]);
        s3b[2] = ffma2(C2b, q1.x, s3b[2]);
        s3b[3] = ffma2(C2b, q1.y, s3b[3]);
        s3b[4] = ffma2(C2b, q2.x, s3b[4]);
        s3b[5] = ffma2(C2b, q2.y, s3b[5]);
        s3b[6] = ffma2(C2b, q3.x, s3b[6]);
        s3b[7] = ffma2(C2b, q3.y, s3b[7]);
        s3b[0] = ffma2(K3l, v0.x, s3b[0]);
        s3b[1] = ffma2(K3l, v0.y, s3b[1]);
        s3b[2] = ffma2(K3l, v1.x, s3b[2]);
        s3b[3] = ffma2(K3l, v1.y, s3b[3]);
        s2b = fmaf(-Da, S1b, fmaf(0.5f * Da, Db, s2b));
        s2g = fmaf(-Da, S1b8, s2g);
    } else {
        const u64 C2b = bcast2(t);
        const u64 C2g = bcast2(0.5f * t);
        const u64 K3h = bcast2(-0.5f * t);
        const u64 K36 = bcast2(-t * (1.0f / 6.0f));
        s3b[0] = ffma2(C2b, q0.x, s3b[0]);
        s3b[1] = ffma2(C2b, q0.y, s3b[1]);
        s3b[2] = ffma2(C2b, q1.x, s3b[2]);
        s3b[3] = ffma2(C2b, q1.y, s3b[3]);
        s3b[4] = ffma2(C2b, q2.x, s3b[4]);
        s3b[5] = ffma2(C2b, q2.y, s3b[5]);
        s3b[6] = ffma2(C2b, q3.x, s3b[6]);
        s3b[7] = ffma2(C2b, q3.y, s3b[7]);
        s3g[0] = ffma2(C2g, q0.x, s3g[0]);
        s3g[1] = ffma2(C2g, q0.y, s3g[1]);
        s3g[2] = ffma2(C2g, q1.x, s3g[2]);
        s3g[3] = ffma2(C2g, q1.y, s3g[3]);
        s3g[4] = ffma2(C2g, q2.x, s3g[4]);
        s3g[5] = ffma2(C2g, q2.y, s3g[5]);
        s3g[6] = ffma2(C2g, q3.x, s3g[6]);
        s3g[7] = ffma2(C2g, q3.y, s3g[7]);
        s3b[0] = ffma2(K3h, v0.x, s3b[0]);
        s3b[1] = ffma2(K3h, v0.y, s3b[1]);
        s3b[2] = ffma2(K3h, v1.x, s3b[2]);
        s3b[3] = ffma2(K3h, v1.y, s3b[3]);
        s3g[0] = ffma2(K3h, v0.x, s3g[0]);
        s3g[1] = ffma2(K3h, v0.y, s3g[1]);
        s3g[2] = ffma2(K3h, v1.x, s3g[2]);
        s3g[3] = ffma2(K3h, v1.y, s3g[3]);
        s3g[4] = ffma2(K36, v0.x, s3g[4]);
        s3g[5] = ffma2(K36, v0.y, s3g[5]);
        s3g[6] = ffma2(K36, v1.x, s3g[6]);
        s3g[7] = ffma2(K36, v1.y, s3g[7]);
        s2b = fmaf(-Da, S1b, fmaf(Da, Db, s2b));
        s2g = fmaf(-Da, S1b8, fmaf(0.5f * Da, Db, s2g));
    }
    s1a -= Da;
}

// Stage this thread's two S3 rows into a SW128-swizzled tile (conflict-free).
__device__ __forceinline__ void stage_tile(char* __restrict__ tbytes,
                                           int a, int b,
                                           const u64* s3b, const u64* s3g)
{
    const unsigned int rb = (unsigned)(a * LLD + b);
    const unsigned int rg = rb + 8;
#pragma unroll
    for (int k = 0; k < 4; ++k) {
        const unsigned int ob = sw128(rb * 64u + k * 16u);
        const unsigned int og = sw128(rg * 64u + k * 16u);
        *reinterpret_cast<ulonglong2*>(tbytes + ob) =
            make_ulonglong2(s3b[2 * k], s3b[2 * k + 1]);
        *reinterpret_cast<ulonglong2*>(tbytes + og) =
            make_ulonglong2(s3g[2 * k], s3g[2 * k + 1]);
    }
}

__device__ __forceinline__ void tma_store_tile(const CUtensorMap* tmap,
                                               const char* tile, int pos)
{
    asm volatile("fence.proxy.async.shared::cta;" ::: "memory");
    const unsigned int src = smem_u32(tile);
    const int cy = pos * 128;
    asm volatile(
        "cp.async.bulk.tensor.2d.global.shared::cta.tile.bulk_group "
        "[%0, {%1, %2}], [%3];"
        :: "l"(tmap), "r"(0), "r"(cy), "r"(src) : "memory");
    asm volatile("cp.async.bulk.commit_group;" ::: "memory");
}

__global__ void __launch_bounds__(128, 5)
leadlag_sig_kernel(const float* __restrict__ x,
                   float* __restrict__ out1,
                   float* __restrict__ out2,
                   const __grid_constant__ CUtensorMap tmap,
                   int seq_len)
{
    extern __shared__ __align__(16) char dynsmem[];
    char*  tiles = dynsmem;                                      // 2 SW128 tiles
    float* sd    = reinterpret_cast<float*>(dynsmem + SD_OFF);
    float* s2bufA = reinterpret_cast<float*>(dynsmem + S2_OFF);  // 16 x 20 floats
    float* s2bufB = s2bufA + 16 * 20;
    float* s1bufA = reinterpret_cast<float*>(dynsmem + S1_OFF);  // 16 floats
    float* s1bufB = s1bufA + 16;

    const int p0  = blockIdx.x * CHUNK;
    const int tid = threadIdx.x;

    // 18 diffs: diff t uses x rows (p0 + t - 15, p0 + t - 14)
    for (int j = tid; j < NDT * DIM; j += 128) {
        int t = j >> 3;
        int c = j & 7;
        int r0 = p0 + t - (PATCH - 1);
        int r1 = r0 + 1;
        float q0 = (r0 >= 0) ? x[r0 * DIM + c] : 0.0f;
        float q1 = (r1 >= 0) ? x[r1 * DIM + c] : 0.0f;
        sd[j] = q1 - q0;
    }
    __syncthreads();

    const int a  = tid >> 3;   // 0..15
    const int b  = tid & 7;    // lead column; lag column is b+8
    const int ai = a & 7;

    u64 s3b[8], s3g[8];
#pragma unroll
    for (int k = 0; k < 8; ++k) { s3b[k] = 0ULL; s3g[k] = 0ULL; }
    float s2b = 0.0f, s2g = 0.0f, s1a = 0.0f;

    // ---- full recursion for position p0 (diffs 0..14) ----
    if (a < 8) {
#pragma unroll
        for (int t = 0; t < NDIFF; ++t)
            right_pair<true>(sd + t * 8, ai, b, s3b, s3g, s2b, s2g, s1a);
    } else {
#pragma unroll
        for (int t = 0; t < NDIFF; ++t)
            right_pair<false>(sd + t * 8, ai, b, s3b, s3g, s2b, s2g, s1a);
    }

    // hand off state + small outputs + stage pos0
    s2bufA[a * 20 + b]     = s2b;
    s2bufA[a * 20 + b + 8] = s2g;
    if (b == 0) s1bufA[a] = s1a;
    if (b == 0) out1[p0 * LLD + a] = s1a;
    {
        const int r2 = p0 * (LLD * LLD) + a * LLD + b;
        out2[r2]     = s2b;
        out2[r2 + 8] = s2g;
    }
    stage_tile(tiles, a, b, s3b, s3g);
    __syncthreads();

    if (tid == 0) tma_store_tile(&tmap, tiles, p0);

    // ---- slides: positions p0+1 .. p0+3 ----
#pragma unroll 1
    for (int s = 1; s < CHUNK; ++s) {
        float* s2prev = (s & 1) ? s2bufA : s2bufB;
        float* s2cur  = (s & 1) ? s2bufB : s2bufA;
        float* s1prev = (s & 1) ? s1bufA : s1bufB;
        float* s1cur  = (s & 1) ? s1bufB : s1bufA;
        char*  tcur   = tiles + (s & 1) * TILE_BYTES;
        const float* dOld = sd + (s - 1) * 8;
        const float* dNew = sd + (s + NDIFF - 1) * 8;

        if (a < 8) {
            left_remove<true >(dOld, s2prev + b * 20, s2prev + (b + 8) * 20,
                               s1prev, ai, b, s3b, s3g, s2b, s2g, s1a);
            right_pair<true >(dNew, ai, b, s3b, s3g, s2b, s2g, s1a);
        } else {
            left_remove<false>(dOld, s2prev + b * 20, s2prev + (b + 8) * 20,
                               s1prev, ai, b, s3b, s3g, s2b, s2g, s1a);
            right_pair<false>(dNew, ai, b, s3b, s3g, s2b, s2g, s1a);
        }

        // gate tile reuse: the store issued 2 slides ago must have drained
        if (tid == 0) {
            asm volatile("cp.async.bulk.wait_group 1;" ::: "memory");
        }
        __syncthreads();   // propagates tid0's wait; also closes s2prev readers

        const int p = p0 + s;
        s2cur[a * 20 + b]     = s2b;
        s2cur[a * 20 + b + 8] = s2g;
        if (b == 0) s1cur[a] = s1a;
        if (b == 0) out1[p * LLD + a] = s1a;
        {
            const int r2 = p * (LLD * LLD) + a * LLD + b;
            out2[r2]     = s2b;
            out2[r2 + 8] = s2g;
        }
        stage_tile(tcur, a, b, s3b, s3g);
        __syncthreads();

        if (tid == 0) tma_store_tile(&tmap, tcur, p);
    }

    if (tid == 0) {
        asm volatile("cp.async.bulk.wait_group 0;" ::: "memory");
    }
}

// Driver-API entry point resolved through cudart (harness links cudart only).
typedef CUresult (*EncodeTiledFn)(
    CUtensorMap*, CUtensorMapDataType, cuuint32_t, void*,
    const cuuint64_t*, const cuuint64_t*, const cuuint32_t*, const cuuint32_t*,
    CUtensorMapInterleave, CUtensorMapSwizzle, CUtensorMapL2promotion,
    CUtensorMapFloatOOBfill);

extern "C" void kernel_launch(void* const* d_in, const int* in_sizes, int n_in,
                              void* d_out, int out_size)
{
    const float* x = (const float*)d_in[0];
    const int seq_len = in_sizes[0] / DIM;

    float* out = (float*)d_out;
    float* out1 = out;
    float* out2 = out + (size_t)seq_len * LLD;
    float* out3 = out + (size_t)seq_len * LLD + (size_t)seq_len * LLD * LLD;

    void* fn = nullptr;
    cudaDriverEntryPointQueryResult qres = cudaDriverEntryPointSymbolNotFound;
    cudaGetDriverEntryPoint("cuTensorMapEncodeTiled", &fn,
                            cudaEnableDefault, &qres);
    EncodeTiledFn encode = (EncodeTiledFn)fn;

    // 2D view of out3: rows of 32 floats (128 B), seq_len*128 rows total.
    CUtensorMap tmap;
    cuuint64_t dims[2]    = { 32ull, (cuuint64_t)seq_len * 128ull };
    cuuint64_t strides[1] = { 128ull };
    cuuint32_t box[2]     = { 32u, 128u };
    cuuint32_t estr[2]    = { 1u, 1u };
    encode(&tmap, CU_TENSOR_MAP_DATA_TYPE_FLOAT32, 2, (void*)out3,
           dims, strides, box, estr,
           CU_TENSOR_MAP_INTERLEAVE_NONE,
           CU_TENSOR_MAP_SWIZZLE_128B,
           CU_TENSOR_MAP_L2_PROMOTION_L2_128B,
           CU_TENSOR_MAP_FLOAT_OOB_FILL_NONE);

    leadlag_sig_kernel<<<seq_len / CHUNK, 128, SMEM_TOTAL>>>(x, out1, out2, tmap, seq_len);
}

// round 15
// speedup vs baseline: 1.0535x; 1.0535x over previous
#include <cuda_runtime.h>
#include <cuda.h>

// LeadLagSignature depth-3, lead-lag of 16-point sliding patches.
// R14 = R11 (CHUNK=2 sliding Chen + SW128 tiles + TMA bulk stores) with
// occupancy push: __launch_bounds__(128,6) and left_remove restructured
// column-by-column to cut peak register pressure (fit 85 regs w/o spills).

#define DIM 8
#define PATCH 16
#define NDIFF 15
#define LLD 16
#define NDT 16                                   // diffs needed for 2 positions
#define TILE_BYTES (LLD * LLD * LLD * 4)         // 16384
#define SD_OFF     (2 * TILE_BYTES)              // 32768
#define S2_OFF     (SD_OFF + NDT * DIM * 4)      // +512
#define S1_OFF     (S2_OFF + 16 * 20 * 4)        // +1280
#define SMEM_TOTAL (S1_OFF + 16 * 4)             // 34688

typedef unsigned long long u64;

__device__ __forceinline__ u64 ffma2(u64 a, u64 b, u64 c) {
    u64 d;
    asm("fma.rn.f32x2 %0, %1, %2, %3;" : "=l"(d) : "l"(a), "l"(b), "l"(c));
    return d;
}

__device__ __forceinline__ u64 bcast2(float f) {
    unsigned int r = __float_as_uint(f);
    u64 d;
    asm("mov.b64 %0, {%1, %1};" : "=l"(d) : "r"(r));
    return d;
}

__device__ __forceinline__ unsigned int smem_u32(const void* p) {
    unsigned int a;
    asm("{ .reg .u64 t; cvta.to.shared.u64 t, %1; cvt.u32.u64 %0, t; }"
        : "=r"(a) : "l"(p));
    return a;
}

__device__ __forceinline__ unsigned int sw128(unsigned int byte_off) {
    return byte_off ^ ((byte_off >> 3) & 0x70);
}

// ---- right-append of the two increments (lead then lag) of diff vector dv ----
template <bool ALEAD>
__device__ __forceinline__ void right_pair(const float* __restrict__ dv,
                                           int ai, int bi,
                                           u64* s3b, u64* s3g,
                                           float& s2b, float& s2g, float& s1a)
{
    const float C2 = 0.5f;
    const float C3 = 1.0f / 6.0f;
    const ulonglong2 pA = *reinterpret_cast<const ulonglong2*>(dv);
    const ulonglong2 pB = *reinterpret_cast<const ulonglong2*>(dv + 4);
    const float va = dv[ai];
    const float vb = dv[bi];

    float Fb, F2b, Fg, F2g;
    if (ALEAD) {
        Fg = s2g;
        const float cs1 = C2 * s1a;
        const float u   = fmaf(C3, va, cs1);
        Fb  = fmaf(vb, u, s2b);
        const float w   = fmaf(C2, va, s1a);
        s2b = fmaf(vb, w, s2b);
        s1a += va;
        F2b = s2b;
        const float h   = C2 * s1a;
        F2g = fmaf(vb, h, s2g);
        s2g = fmaf(vb, s1a, s2g);
    } else {
        const float cs1 = C2 * s1a;
        Fb  = fmaf(vb, cs1, s2b);
        s2b = fmaf(vb, s1a, s2b);
        Fg  = s2g;
        F2b = s2b;
        const float u   = fmaf(C3, va, cs1);
        F2g = fmaf(vb, u, s2g);
        const float w   = fmaf(C2, va, s1a);
        s2g = fmaf(vb, w, s2g);
        s1a += va;
    }

    const u64 Fbp  = bcast2(Fb);
    const u64 F2bp = bcast2(F2b);
    const u64 Fgp  = bcast2(Fg);
    const u64 F2gp = bcast2(F2g);

    s3b[0] = ffma2(Fbp,  pA.x, s3b[0]);
    s3b[1] = ffma2(Fbp,  pA.y, s3b[1]);
    s3b[2] = ffma2(Fbp,  pB.x, s3b[2]);
    s3b[3] = ffma2(Fbp,  pB.y, s3b[3]);
    s3b[4] = ffma2(F2bp, pA.x, s3b[4]);
    s3b[5] = ffma2(F2bp, pA.y, s3b[5]);
    s3b[6] = ffma2(F2bp, pB.x, s3b[6]);
    s3b[7] = ffma2(F2bp, pB.y, s3b[7]);
    s3g[0] = ffma2(Fgp,  pA.x, s3g[0]);
    s3g[1] = ffma2(Fgp,  pA.y, s3g[1]);
    s3g[2] = ffma2(Fgp,  pB.x, s3g[2]);
    s3g[3] = ffma2(Fgp,  pB.y, s3g[3]);
    s3g[4] = ffma2(F2gp, pA.x, s3g[4]);
    s3g[5] = ffma2(F2gp, pA.y, s3g[5]);
    s3g[6] = ffma2(F2gp, pB.x, s3g[6]);
    s3g[7] = ffma2(F2gp, pB.y, s3g[7]);
}

// ---- combined left-removal by C = e^{-G(d)} ⊗ e^{-L(d)} (math verified R5/R11),
// restructured per-column to lower peak register pressure ----
template <bool ALEAD>
__device__ __forceinline__ void left_remove(const float* __restrict__ dOld,
                                            const float* __restrict__ s2rowb,
                                            const float* __restrict__ s2rowg,
                                            const float* __restrict__ s1old,
                                            int ai, int b,
                                            u64* s3b, u64* s3g,
                                            float& s2b, float& s2g, float& s1a)
{
    const float Da = dOld[ai];
    const float Db = dOld[b];
    const ulonglong2 v0 = *reinterpret_cast<const ulonglong2*>(dOld);
    const ulonglong2 v1 = *reinterpret_cast<const ulonglong2*>(dOld + 4);
    const u64 C1 = bcast2(-Da);
    const float t = Da * Db;

    const ulonglong2 q0 = *reinterpret_cast<const ulonglong2*>(s1old);
    const ulonglong2 q1 = *reinterpret_cast<const ulonglong2*>(s1old + 4);
    const ulonglong2 q2 = *reinterpret_cast<const ulonglong2*>(s1old + 8);
    const ulonglong2 q3 = *reinterpret_cast<const ulonglong2*>(s1old + 12);

    // ===== column b =====
    {
        const ulonglong2 rb0 = *reinterpret_cast<const ulonglong2*>(s2rowb);
        const ulonglong2 rb1 = *reinterpret_cast<const ulonglong2*>(s2rowb + 4);
        const ulonglong2 rb2 = *reinterpret_cast<const ulonglong2*>(s2rowb + 8);
        const ulonglong2 rb3 = *reinterpret_cast<const ulonglong2*>(s2rowb + 12);
        s3b[0] = ffma2(C1, rb0.x, s3b[0]);
        s3b[1] = ffma2(C1, rb0.y, s3b[1]);
        s3b[2] = ffma2(C1, rb1.x, s3b[2]);
        s3b[3] = ffma2(C1, rb1.y, s3b[3]);
        s3b[4] = ffma2(C1, rb2.x, s3b[4]);
        s3b[5] = ffma2(C1, rb2.y, s3b[5]);
        s3b[6] = ffma2(C1, rb3.x, s3b[6]);
        s3b[7] = ffma2(C1, rb3.y, s3b[7]);

        const u64 C2b = bcast2(ALEAD ? 0.5f * t : t);
        s3b[0] = ffma2(C2b, q0.x, s3b[0]);
        s3b[1] = ffma2(C2b, q0.y, s3b[1]);
        s3b[2] = ffma2(C2b, q1.x, s3b[2]);
        s3b[3] = ffma2(C2b, q1.y, s3b[3]);
        s3b[4] = ffma2(C2b, q2.x, s3b[4]);
        s3b[5] = ffma2(C2b, q2.y, s3b[5]);
        s3b[6] = ffma2(C2b, q3.x, s3b[6]);
        s3b[7] = ffma2(C2b, q3.y, s3b[7]);

        const u64 K3b = bcast2(ALEAD ? -t * (1.0f / 6.0f) : -0.5f * t);
        s3b[0] = ffma2(K3b, v0.x, s3b[0]);
        s3b[1] = ffma2(K3b, v0.y, s3b[1]);
        s3b[2] = ffma2(K3b, v1.x, s3b[2]);
        s3b[3] = ffma2(K3b, v1.y, s3b[3]);

        const float S1b = s1old[b];
        if (ALEAD) s2b = fmaf(-Da, S1b, fmaf(0.5f * Da, Db, s2b));
        else       s2b = fmaf(-Da, S1b, fmaf(Da, Db, s2b));
    }

    // ===== column b+8 =====
    {
        const ulonglong2 rg0 = *reinterpret_cast<const ulonglong2*>(s2rowg);
        const ulonglong2 rg1 = *reinterpret_cast<const ulonglong2*>(s2rowg + 4);
        const ulonglong2 rg2 = *reinterpret_cast<const ulonglong2*>(s2rowg + 8);
        const ulonglong2 rg3 = *reinterpret_cast<const ulonglong2*>(s2rowg + 12);
        s3g[0] = ffma2(C1, rg0.x, s3g[0]);
        s3g[1] = ffma2(C1, rg0.y, s3g[1]);
        s3g[2] = ffma2(C1, rg1.x, s3g[2]);
        s3g[3] = ffma2(C1, rg1.y, s3g[3]);
        s3g[4] = ffma2(C1, rg2.x, s3g[4]);
        s3g[5] = ffma2(C1, rg2.y, s3g[5]);
        s3g[6] = ffma2(C1, rg3.x, s3g[6]);
        s3g[7] = ffma2(C1, rg3.y, s3g[7]);

        if (!ALEAD) {
            const u64 C2g = bcast2(0.5f * t);
            s3g[0] = ffma2(C2g, q0.x, s3g[0]);
            s3g[1] = ffma2(C2g, q0.y, s3g[1]);
            s3g[2] = ffma2(C2g, q1.x, s3g[2]);
            s3g[3] = ffma2(C2g, q1.y, s3g[3]);
            s3g[4] = ffma2(C2g, q2.x, s3g[4]);
            s3g[5] = ffma2(C2g, q2.y, s3g[5]);
            s3g[6] = ffma2(C2g, q3.x, s3g[6]);
            s3g[7] = ffma2(C2g, q3.y, s3g[7]);
            const u64 K3h = bcast2(-0.5f * t);
            const u64 K36 = bcast2(-t * (1.0f / 6.0f));
            s3g[0] = ffma2(K3h, v0.x, s3g[0]);
            s3g[1] = ffma2(K3h, v0.y, s3g[1]);
            s3g[2] = ffma2(K3h, v1.x, s3g[2]);
            s3g[3] = ffma2(K3h, v1.y, s3g[3]);
            s3g[4] = ffma2(K36, v0.x, s3g[4]);
            s3g[5] = ffma2(K36, v0.y, s3g[5]);
            s3g[6] = ffma2(K36, v1.x, s3g[6]);
            s3g[7] = ffma2(K36, v1.y, s3g[7]);
        }

        const float S1b8 = s1old[b + 8];
        if (ALEAD) s2g = fmaf(-Da, S1b8, s2g);
        else       s2g = fmaf(-Da, S1b8, fmaf(0.5f * Da, Db, s2g));
    }

    s1a -= Da;
}

// Stage this thread's two S3 rows into a SW128-swizzled tile (conflict-free).
__device__ __forceinline__ void stage_tile(char* __restrict__ tbytes,
                                           int a, int b,
                                           const u64* s3b, const u64* s3g)
{
    const unsigned int rb = (unsigned)(a * LLD + b);
    const unsigned int rg = rb + 8;
#pragma unroll
    for (int k = 0; k < 4; ++k) {
        const unsigned int ob = sw128(rb * 64u + k * 16u);
        const unsigned int og = sw128(rg * 64u + k * 16u);
        *reinterpret_cast<ulonglong2*>(tbytes + ob) =
            make_ulonglong2(s3b[2 * k], s3b[2 * k + 1]);
        *reinterpret_cast<ulonglong2*>(tbytes + og) =
            make_ulonglong2(s3g[2 * k], s3g[2 * k + 1]);
    }
}

__global__ void __launch_bounds__(128, 6)
leadlag_sig_kernel(const float* __restrict__ x,
                   float* __restrict__ out1,
                   float* __restrict__ out2,
                   const __grid_constant__ CUtensorMap tmap,
                   int seq_len)
{
    extern __shared__ __align__(16) char dynsmem[];
    char*  tile0 = dynsmem;                                  // SW128 tiles, atom-aligned
    char*  tile1 = dynsmem + TILE_BYTES;
    float* sd    = reinterpret_cast<float*>(dynsmem + SD_OFF);
    float* s2buf = reinterpret_cast<float*>(dynsmem + S2_OFF);   // 16 rows x 20 floats
    float* s1buf = reinterpret_cast<float*>(dynsmem + S1_OFF);   // 16 floats

    const int p0  = blockIdx.x * 2;
    const int tid = threadIdx.x;

    // 16 diffs: diff t uses x rows (p0 + t - 15, p0 + t - 14)
    {
        int t = tid >> 3;
        int c = tid & 7;
        int r0 = p0 + t - (PATCH - 1);
        int r1 = r0 + 1;
        float q0 = (r0 >= 0) ? x[r0 * DIM + c] : 0.0f;
        float q1 = (r1 >= 0) ? x[r1 * DIM + c] : 0.0f;
        sd[tid] = q1 - q0;
    }
    __syncthreads();

    const int a  = tid >> 3;   // 0..15
    const int b  = tid & 7;    // lead column; lag column is b+8
    const int ai = a & 7;

    u64 s3b[8], s3g[8];
#pragma unroll
    for (int k = 0; k < 8; ++k) { s3b[k] = 0ULL; s3g[k] = 0ULL; }
    float s2b = 0.0f, s2g = 0.0f, s1a = 0.0f;

    // ---- full recursion for position p0 (diffs 0..14) ----
    if (a < 8) {
#pragma unroll
        for (int t = 0; t < NDIFF; ++t)
            right_pair<true>(sd + t * 8, ai, b, s3b, s3g, s2b, s2g, s1a);
    } else {
#pragma unroll
        for (int t = 0; t < NDIFF; ++t)
            right_pair<false>(sd + t * 8, ai, b, s3b, s3g, s2b, s2g, s1a);
    }

    // hand off S2/S1 state for the slide
    s2buf[a * 20 + b]     = s2b;
    s2buf[a * 20 + b + 8] = s2g;
    if (b == 0) s1buf[a] = s1a;

    // small outputs pos0
    if (b == 0) out1[p0 * LLD + a] = s1a;
    {
        const int r2 = p0 * (LLD * LLD) + a * LLD + b;
        out2[r2]     = s2b;
        out2[r2 + 8] = s2g;
    }

    stage_tile(tile0, a, b, s3b, s3g);
    __syncthreads();

    // launch pos0 TMA store (no wait — overlaps the slide compute)
    if (tid == 0) {
        asm volatile("fence.proxy.async.shared::cta;" ::: "memory");
        const unsigned int src = smem_u32(tile0);
        const int cy = p0 * 128;
        asm volatile(
            "cp.async.bulk.tensor.2d.global.shared::cta.tile.bulk_group "
            "[%0, {%1, %2}], [%3];"
            :: "l"(&tmap), "r"(0), "r"(cy), "r"(src) : "memory");
        asm volatile("cp.async.bulk.commit_group;" ::: "memory");
    }

    // ---- slide to pos p0+1: remove diff 0, append diff 15 ----
    if (a < 8) {
        left_remove<true >(sd, s2buf + b * 20, s2buf + (b + 8) * 20,
                           s1buf, ai, b, s3b, s3g, s2b, s2g, s1a);
        right_pair<true >(sd + NDIFF * 8, ai, b, s3b, s3g, s2b, s2g, s1a);
    } else {
        left_remove<false>(sd, s2buf + b * 20, s2buf + (b + 8) * 20,
                           s1buf, ai, b, s3b, s3g, s2b, s2g, s1a);
        right_pair<false>(sd + NDIFF * 8, ai, b, s3b, s3g, s2b, s2g, s1a);
    }

    // small outputs pos1
    const int p1 = p0 + 1;
    if (b == 0) out1[p1 * LLD + a] = s1a;
    {
        const int r2 = p1 * (LLD * LLD) + a * LLD + b;
        out2[r2]     = s2b;
        out2[r2 + 8] = s2g;
    }

    stage_tile(tile1, a, b, s3b, s3g);
    __syncthreads();

    if (tid == 0) {
        asm volatile("fence.proxy.async.shared::cta;" ::: "memory");
        const unsigned int src = smem_u32(tile1);
        const int cy = p1 * 128;
        asm volatile(
            "cp.async.bulk.tensor.2d.global.shared::cta.tile.bulk_group "
            "[%0, {%1, %2}], [%3];"
            :: "l"(&tmap), "r"(0), "r"(cy), "r"(src) : "memory");
        asm volatile("cp.async.bulk.commit_group;" ::: "memory");
        asm volatile("cp.async.bulk.wait_group 0;" ::: "memory");
    }
}

// Driver-API entry point resolved through cudart (harness links cudart only).
typedef CUresult (*EncodeTiledFn)(
    CUtensorMap*, CUtensorMapDataType, cuuint32_t, void*,
    const cuuint64_t*, const cuuint64_t*, const cuuint32_t*, const cuuint32_t*,
    CUtensorMapInterleave, CUtensorMapSwizzle, CUtensorMapL2promotion,
    CUtensorMapFloatOOBfill);

extern "C" void kernel_launch(void* const* d_in, const int* in_sizes, int n_in,
                              void* d_out, int out_size)
{
    const float* x = (const float*)d_in[0];
    const int seq_len = in_sizes[0] / DIM;

    float* out = (float*)d_out;
    float* out1 = out;
    float* out2 = out + (size_t)seq_len * LLD;
    float* out3 = out + (size_t)seq_len * LLD + (size_t)seq_len * LLD * LLD;

    void* fn = nullptr;
    cudaDriverEntryPointQueryResult qres = cudaDriverEntryPointSymbolNotFound;
    cudaGetDriverEntryPoint("cuTensorMapEncodeTiled", &fn,
                            cudaEnableDefault, &qres);
    EncodeTiledFn encode = (EncodeTiledFn)fn;

    // 2D view of out3: rows of 32 floats (128 B), seq_len*128 rows total.
    CUtensorMap tmap;
    cuuint64_t dims[2]    = { 32ull, (cuuint64_t)seq_len * 128ull };
    cuuint64_t strides[1] = { 128ull };
    cuuint32_t box[2]     = { 32u, 128u };
    cuuint32_t estr[2]    = { 1u, 1u };
    encode(&tmap, CU_TENSOR_MAP_DATA_TYPE_FLOAT32, 2, (void*)out3,
           dims, strides, box, estr,
           CU_TENSOR_MAP_INTERLEAVE_NONE,
           CU_TENSOR_MAP_SWIZZLE_128B,
           CU_TENSOR_MAP_L2_PROMOTION_L2_128B,
           CU_TENSOR_MAP_FLOAT_OOB_FILL_NONE);

    leadlag_sig_kernel<<<seq_len / 2, 128, SMEM_TOTAL>>>(x, out1, out2, tmap, seq_len);
}